// round 5
// baseline (speedup 1.0000x reference)
#include <cuda_runtime.h>

// Reverse cummax along axis 1 of [B=16, H=128, W=128, C=256] fp32.
// out[b,h,w,c] = max_{h'>=h} in[b,h',w,c]
//
// One thread per (b, w, c4) float4 column, register running max, h=127..0.
// Block size 128 -> grid 1024 CTAs: per-SM CTA counts are 7 vs 6
// (1.2% imbalance) instead of 4 vs 3 (33%) at block 256. All CTAs are
// co-resident; balance, not latency, sets the tail.
// Streaming hints (__ldcs/__stcs): zero reuse, keep L2 evict-first.
//
// (Resubmission of R3 kernel: R4 bench died with "device busy" at harness
//  init — infra transient, kernel never executed.)

static constexpr int B = 16;
static constexpr int H = 128;
static constexpr int W = 128;
static constexpr int C = 256;
static constexpr int C4 = C / 4;                 // 64 float4 per (w) row
static constexpr int PLANE4 = W * C4;            // 8192 float4 per (b,h) slice
static constexpr int HSTRIDE4 = PLANE4;
static constexpr int NCOL = B * W * C4;          // 131072 columns

__global__ __launch_bounds__(128) void suffix_cummax_kernel(
    const float4* __restrict__ in, float4* __restrict__ out)
{
    int col = blockIdx.x * blockDim.x + threadIdx.x;  // grid covers exactly NCOL

    // col -> (b, w, c4): c4 fastest
    int c4 = col & (C4 - 1);
    int w  = (col >> 6) & (W - 1);       // C4 = 2^6
    int b  = col >> 13;                  // W*C4 = 2^13

    long long base = (long long)b * H * PLANE4 + (long long)w * C4 + c4;

    const float4* ip = in  + base + (long long)(H - 1) * HSTRIDE4;
    float4*       op = out + base + (long long)(H - 1) * HSTRIDE4;

    float4 run;
    run.x = -__int_as_float(0x7f800000);  // -inf
    run.y = run.x; run.z = run.x; run.w = run.x;

    #pragma unroll 4
    for (int h = H - 1; h >= 0; --h) {
        float4 v = __ldcs(ip);
        run.x = fmaxf(run.x, v.x);
        run.y = fmaxf(run.y, v.y);
        run.z = fmaxf(run.z, v.z);
        run.w = fmaxf(run.w, v.w);
        __stcs(op, run);
        ip -= HSTRIDE4;
        op -= HSTRIDE4;
    }
}

extern "C" void kernel_launch(void* const* d_in, const int* in_sizes, int n_in,
                              void* d_out, int out_size)
{
    const float4* in  = (const float4*)d_in[0];
    float4*       out = (float4*)d_out;

    int threads = 128;
    int blocks  = NCOL / threads;  // 1024, exact
    suffix_cummax_kernel<<<blocks, threads>>>(in, out);
}

// round 8
// speedup vs baseline: 1.1311x; 1.1311x over previous
#include <cuda_runtime.h>

// Reverse cummax along axis 1 of [B=16, H=128, W=128, C=256] fp32.
// out[b,h,w,c] = max_{h'>=h} in[b,h',w,c]
//
// One thread per (b, w, c4) float4 column, register running max, h=127..0.
// Block 256 / grid 512 (the measured-best config). Explicit double-buffered
// software pipeline: prefetch the NEXT 4 h-steps' loads before consuming the
// current 4, so >=4 independent LDG.128 are always in flight per thread.
// Stores issue immediately after their max (no deferred store phase).
// No cache hints — __ldcs/__stcs measured -3..-16% across R2/R5.

static constexpr int B = 16;
static constexpr int H = 128;
static constexpr int W = 128;
static constexpr int C = 256;
static constexpr int C4 = C / 4;                 // 64 float4 per (w) row
static constexpr int PLANE4 = W * C4;            // 8192 float4 per (b,h) slice
static constexpr int HSTRIDE4 = PLANE4;
static constexpr int NCOL = B * W * C4;          // 131072 columns
static constexpr int CHUNK = 4;

__global__ __launch_bounds__(256) void suffix_cummax_kernel(
    const float4* __restrict__ in, float4* __restrict__ out)
{
    int col = blockIdx.x * blockDim.x + threadIdx.x;  // grid covers exactly NCOL

    // col -> (b, w, c4): c4 fastest
    int c4 = col & (C4 - 1);
    int w  = (col >> 6) & (W - 1);       // C4 = 2^6
    int b  = col >> 13;                  // W*C4 = 2^13

    // whole tensor is 16M float4 -> int indexing is safe
    int base = b * (H * PLANE4) + w * C4 + c4;

    const float4* ip = in  + base + (H - 1) * HSTRIDE4;
    float4*       op = out + base + (H - 1) * HSTRIDE4;

    float4 run;
    run.x = -__int_as_float(0x7f800000);  // -inf
    run.y = run.x; run.z = run.x; run.w = run.x;

    // Prologue: prefetch first chunk (h = 127..124)
    float4 p[CHUNK];
    #pragma unroll
    for (int j = 0; j < CHUNK; ++j)
        p[j] = ip[-j * HSTRIDE4];
    ip -= CHUNK * HSTRIDE4;

    // Steady state: issue next chunk's loads, then max+store current chunk.
    #pragma unroll 1
    for (int it = 0; it < H / CHUNK - 1; ++it) {
        float4 v[CHUNK];
        #pragma unroll
        for (int j = 0; j < CHUNK; ++j)
            v[j] = p[j];

        #pragma unroll
        for (int j = 0; j < CHUNK; ++j)
            p[j] = ip[-j * HSTRIDE4];        // next chunk, in flight
        ip -= CHUNK * HSTRIDE4;

        #pragma unroll
        for (int j = 0; j < CHUNK; ++j) {
            run.x = fmaxf(run.x, v[j].x);
            run.y = fmaxf(run.y, v[j].y);
            run.z = fmaxf(run.z, v[j].z);
            run.w = fmaxf(run.w, v[j].w);
            op[-j * HSTRIDE4] = run;
        }
        op -= CHUNK * HSTRIDE4;
    }

    // Epilogue: last chunk (h = 3..0)
    #pragma unroll
    for (int j = 0; j < CHUNK; ++j) {
        run.x = fmaxf(run.x, p[j].x);
        run.y = fmaxf(run.y, p[j].y);
        run.z = fmaxf(run.z, p[j].z);
        run.w = fmaxf(run.w, p[j].w);
        op[-j * HSTRIDE4] = run;
    }
}

extern "C" void kernel_launch(void* const* d_in, const int* in_sizes, int n_in,
                              void* d_out, int out_size)
{
    const float4* in  = (const float4*)d_in[0];
    float4*       out = (float4*)d_out;

    int threads = 256;
    int blocks  = NCOL / threads;  // 512, exact
    suffix_cummax_kernel<<<blocks, threads>>>(in, out);
}

// round 9
// speedup vs baseline: 1.1503x; 1.0169x over previous
#include <cuda_runtime.h>

// Reverse cummax along axis 1 of [B=16, H=128, W=128, C=256] fp32.
// out[b,h,w,c] = max_{h'>=h} in[b,h',w,c]
//
// One thread per (b, w, c4) float4 column, register running max, h=127..0.
// Block 256 / grid 512. Phase-batched: 8 independent LDG.128 issued
// back-to-back, then 8 max+STG.128 — 4KB same-direction bursts per warp to
// cut HBM read/write turnaround (the hypothesized 24% loss at the 76%
// DRAM plateau). NO cache hints: __ldcs/__stcs measured -3..-16% (R2/R5);
// this isolates batching from the hint confound in R2.

static constexpr int B = 16;
static constexpr int H = 128;
static constexpr int W = 128;
static constexpr int C = 256;
static constexpr int C4 = C / 4;                 // 64 float4 per (w) row
static constexpr int PLANE4 = W * C4;            // 8192 float4 per (b,h) slice
static constexpr int HSTRIDE4 = PLANE4;
static constexpr int NCOL = B * W * C4;          // 131072 columns
static constexpr int BATCH = 8;                  // h-steps per load/store phase

__global__ __launch_bounds__(256) void suffix_cummax_kernel(
    const float4* __restrict__ in, float4* __restrict__ out)
{
    int col = blockIdx.x * blockDim.x + threadIdx.x;  // grid covers exactly NCOL

    // col -> (b, w, c4): c4 fastest
    int c4 = col & (C4 - 1);
    int w  = (col >> 6) & (W - 1);       // C4 = 2^6
    int b  = col >> 13;                  // W*C4 = 2^13

    // whole tensor is 16M float4 -> int indexing is safe
    int base = b * (H * PLANE4) + w * C4 + c4;

    const float4* ip = in  + base + (H - 1) * HSTRIDE4;
    float4*       op = out + base + (H - 1) * HSTRIDE4;

    float4 run;
    run.x = -__int_as_float(0x7f800000);  // -inf
    run.y = run.x; run.z = run.x; run.w = run.x;

    #pragma unroll 1
    for (int it = 0; it < H / BATCH; ++it) {
        float4 v[BATCH];
        // Phase 1: burst of 8 independent reads (plain LDG.128, no hints)
        #pragma unroll
        for (int j = 0; j < BATCH; ++j)
            v[j] = ip[-j * HSTRIDE4];
        ip -= BATCH * HSTRIDE4;

        // Phase 2: running max + burst of 8 writes
        #pragma unroll
        for (int j = 0; j < BATCH; ++j) {
            run.x = fmaxf(run.x, v[j].x);
            run.y = fmaxf(run.y, v[j].y);
            run.z = fmaxf(run.z, v[j].z);
            run.w = fmaxf(run.w, v[j].w);
            op[-j * HSTRIDE4] = run;
        }
        op -= BATCH * HSTRIDE4;
    }
}

extern "C" void kernel_launch(void* const* d_in, const int* in_sizes, int n_in,
                              void* d_out, int out_size)
{
    const float4* in  = (const float4*)d_in[0];
    float4*       out = (float4*)d_out;

    int threads = 256;
    int blocks  = NCOL / threads;  // 512, exact
    suffix_cummax_kernel<<<blocks, threads>>>(in, out);
}